// round 2
// baseline (speedup 1.0000x reference)
#include <cuda_runtime.h>
#include <cuda_bf16.h>

// Problem constants
#define NTOK   4096      // B*S
#define DIN    2048
#define DOUT   2048
#define NEXP   16
#define RANK   16
#define TOPK   2
#define NASSIGN (NTOK*TOPK)   // 8192
#define ALPHA  2.0f
#define DSPLIT 4              // phase-A reduction split
#define TILE_T 128            // tokens per tile
#define MAX_TILES 64          // >= 16 + 4096/128 = 48

typedef unsigned long long ull;

// ---------------- packed f32x2 helpers (FFMA2 via PTX) ----------------
__device__ __forceinline__ void fma2(ull &acc, ull a, ull b) {
    asm("fma.rn.f32x2 %0, %1, %2, %0;" : "+l"(acc) : "l"(a), "l"(b));
}
__device__ __forceinline__ ull add2(ull a, ull b) {
    ull r; asm("add.rn.f32x2 %0, %1, %2;" : "=l"(r) : "l"(a), "l"(b)); return r;
}
__device__ __forceinline__ float hadd2(ull v) {
    float lo, hi; asm("mov.b64 {%0,%1}, %2;" : "=f"(lo), "=f"(hi) : "l"(v));
    return lo + hi;
}

// ---------------- device scratch (no allocations allowed) ----------------
__device__ int   d_ntiles[2];
__device__ int4  d_tiles[2][MAX_TILES];      // {expert, start, cnt, pad}
__device__ int   d_list[2][NTOK];            // token ids grouped by (k, expert)
__device__ float d_part[DSPLIT][NASSIGN * RANK];  // phase-A partial dots
__device__ float d_gact[NASSIGN * RANK];     // routing*alpha*silu(a)

// ---------------- kernel 1: build per-(k,expert) token lists ----------------
// NOTE: idxs is int32 on device (JAX silently downcasts int64 without x64 mode).
__global__ void build_lists_kernel(const int* __restrict__ idxs) {
    __shared__ int s_cnt[32], s_base[32], s_run[32];
    int tid = threadIdx.x;
    if (tid < 32) s_cnt[tid] = 0;
    __syncthreads();
    for (int i = tid; i < NASSIGN; i += blockDim.x) {
        int e = idxs[i] & 15;
        int k = i & 1;
        atomicAdd(&s_cnt[k * 16 + e], 1);
    }
    __syncthreads();
    if (tid == 0) {
        int o0 = 0, o1 = 0;
        for (int e = 0; e < 16; e++) {
            s_base[e]      = o0; o0 += s_cnt[e];
            s_base[16 + e] = o1; o1 += s_cnt[16 + e];
        }
    }
    __syncthreads();
    if (tid < 32) s_run[tid] = s_base[tid];
    __syncthreads();
    for (int i = tid; i < NASSIGN; i += blockDim.x) {
        int e = idxs[i] & 15;
        int k = i & 1;
        int pos = atomicAdd(&s_run[k * 16 + e], 1);
        d_list[k][pos] = i >> 1;
    }
    __syncthreads();
    if (tid < 2) {
        int k = tid, nt = 0;
        for (int e = 0; e < 16; e++) {
            int c  = s_cnt[k * 16 + e];
            int st = s_base[k * 16 + e];
            for (int o = 0; o < c; o += TILE_T) {
                int cc = c - o; if (cc > TILE_T) cc = TILE_T;
                d_tiles[k][nt] = make_int4(e, st + o, cc, 0);
                nt++;
            }
        }
        d_ntiles[k] = nt;
    }
}

// ---------------- kernel 2: phase A — a[t,r] partial dots (grouped by expert) ----------------
// grid (MAX_TILES, 2, DSPLIT), block 128. thread = token; w broadcast from smem.
__global__ __launch_bounds__(128) void phaseA_kernel(const float* __restrict__ x,
                                                     const float* __restrict__ w_a) {
    int k  = blockIdx.y;
    int ti = blockIdx.x;
    if (ti >= d_ntiles[k]) return;
    int4 tl = d_tiles[k][ti];
    int e = tl.x, start = tl.y, cnt = tl.z;
    int ds = blockIdx.z;

    __shared__ float sx[128 * 68];   // 128 tokens x 64 floats, row pad 68
    __shared__ float sw[16 * 68];
    __shared__ int   s_tok[128];

    int tid = threadIdx.x;
    int jcl = tid < cnt ? tid : (cnt - 1);
    s_tok[tid] = d_list[k][start + jcl];
    __syncthreads();

    const float* wa_e = w_a + (size_t)e * RANK * DIN;
    int dbase0 = ds * (DIN / DSPLIT);   // 512-wide slice

    ull acc[16];
#pragma unroll
    for (int r = 0; r < 16; r++) acc[r] = 0ull;

    for (int ch = 0; ch < (DIN / DSPLIT) / 64; ch++) {   // 8 chunks of 64
        int db = dbase0 + ch * 64;
        // stage x tile: 128 tok x 16 float4
#pragma unroll
        for (int it = 0; it < 16; it++) {
            int l = it * 128 + tid;
            int tok = l >> 4, c4 = l & 15;
            float4 v = *(const float4*)(x + (size_t)s_tok[tok] * DIN + db + c4 * 4);
            *(float4*)(sx + tok * 68 + c4 * 4) = v;
        }
        // stage w chunk: 16 rows x 16 float4
#pragma unroll
        for (int it = 0; it < 2; it++) {
            int l = it * 128 + tid;
            int r = l >> 4, c4 = l & 15;
            *(float4*)(sw + r * 68 + c4 * 4) =
                *(const float4*)(wa_e + (size_t)r * DIN + db + c4 * 4);
        }
        __syncthreads();

        const float* sxr = sx + tid * 68;
#pragma unroll
        for (int c4 = 0; c4 < 16; c4++) {
            ulonglong2 xv = *(const ulonglong2*)(sxr + c4 * 4);
#pragma unroll
            for (int r = 0; r < 16; r++) {
                ulonglong2 wv = *(const ulonglong2*)(sw + r * 68 + c4 * 4); // broadcast
                fma2(acc[r], xv.x, wv.x);
                fma2(acc[r], xv.y, wv.y);
            }
        }
        __syncthreads();
    }

    if (tid < cnt) {
        int a = s_tok[tid] * 2 + k;
        float* p = &d_part[ds][(size_t)a * RANK];
        float4 v;
#pragma unroll
        for (int q = 0; q < 4; q++) {
            v.x = hadd2(acc[q * 4 + 0]);
            v.y = hadd2(acc[q * 4 + 1]);
            v.z = hadd2(acc[q * 4 + 2]);
            v.w = hadd2(acc[q * 4 + 3]);
            *(float4*)(p + q * 4) = v;
        }
    }
}

// ---------------- kernel 3: combine partials + silu + routing*alpha ----------------
__global__ void combine_kernel(const float* __restrict__ routing) {
    int idx = blockIdx.x * blockDim.x + threadIdx.x;   // over NASSIGN*4 float4 groups
    if (idx >= NASSIGN * 4) return;
    int a = idx >> 2, q = idx & 3;
    size_t off = (size_t)a * RANK + q * 4;
    float4 s = *(const float4*)(&d_part[0][off]);
#pragma unroll
    for (int ds = 1; ds < DSPLIT; ds++) {
        float4 p = *(const float4*)(&d_part[ds][off]);
        s.x += p.x; s.y += p.y; s.z += p.z; s.w += p.w;
    }
    float rs = routing[a] * ALPHA;
    float4 g;
    g.x = rs * s.x * (1.0f / (1.0f + __expf(-s.x)));
    g.y = rs * s.y * (1.0f / (1.0f + __expf(-s.y)));
    g.z = rs * s.z * (1.0f / (1.0f + __expf(-s.z)));
    g.w = rs * s.w * (1.0f / (1.0f + __expf(-s.w)));
    *(float4*)(d_gact + off) = g;
}

// ---------------- kernels 4/5: phase B — out (+)= g @ w_b[e]^T, grouped ----------------
// grid (MAX_TILES, DOUT/256), block 256. lane = d (w_b in regs), g broadcast from smem.
template <int KK>
__global__ __launch_bounds__(256) void phaseB_kernel(const float* __restrict__ w_b,
                                                     float* __restrict__ out) {
    int ti = blockIdx.x;
    if (ti >= d_ntiles[KK]) return;
    int4 tl = d_tiles[KK][ti];
    int e = tl.x, start = tl.y, cnt = tl.z;

    __shared__ float sg[128 * 16];
    __shared__ int   s_tok[128];

    int tid = threadIdx.x, lane = tid & 31, w = tid >> 5;
    int d = blockIdx.y * 256 + w * 32 + lane;

    if (tid < 128) {
        int jcl = tid < cnt ? tid : (cnt - 1);
        s_tok[tid] = d_list[KK][start + jcl];
    }
    __syncthreads();
#pragma unroll
    for (int it = 0; it < 2; it++) {
        int l = it * 256 + tid;        // 512 float4 = 128 tok x 4
        int j = l >> 2, q = l & 3;
        int t = s_tok[j];
        *(float4*)(sg + j * 16 + q * 4) =
            *(const float4*)(d_gact + ((size_t)t * 2 + KK) * RANK + q * 4);
    }
    __syncthreads();

    const ulonglong2* wb = (const ulonglong2*)(w_b + ((size_t)e * DOUT + d) * RANK);
    ulonglong2 w0 = wb[0], w1 = wb[1], w2 = wb[2], w3 = wb[3];

    for (int j = 0; j < cnt; j += 2) {
        // token j
        int t0 = s_tok[j];
        const ulonglong2* g0 = (const ulonglong2*)(sg + j * 16);
        ulonglong2 ga = g0[0], gb = g0[1], gc = g0[2], gd = g0[3];
        ull a0 = 0ull, a1 = 0ull;
        fma2(a0, ga.x, w0.x); fma2(a1, ga.y, w0.y);
        fma2(a0, gb.x, w1.x); fma2(a1, gb.y, w1.y);
        fma2(a0, gc.x, w2.x); fma2(a1, gc.y, w2.y);
        fma2(a0, gd.x, w3.x); fma2(a1, gd.y, w3.y);

        bool v1 = (j + 1) < cnt;
        int t1 = v1 ? s_tok[j + 1] : t0;
        const ulonglong2* g1 = (const ulonglong2*)(sg + (v1 ? (j + 1) : j) * 16);
        ulonglong2 ha = g1[0], hb = g1[1], hc = g1[2], hd = g1[3];
        ull b0 = 0ull, b1 = 0ull;
        fma2(b0, ha.x, w0.x); fma2(b1, ha.y, w0.y);
        fma2(b0, hb.x, w1.x); fma2(b1, hb.y, w1.y);
        fma2(b0, hc.x, w2.x); fma2(b1, hc.y, w2.y);
        fma2(b0, hd.x, w3.x); fma2(b1, hd.y, w3.y);

        float r0 = hadd2(add2(a0, a1));
        float r1 = hadd2(add2(b0, b1));
        size_t o0 = (size_t)t0 * DOUT + d;
        size_t o1 = (size_t)t1 * DOUT + d;
        if (KK == 0) {
            out[o0] = r0;
            if (v1) out[o1] = r1;
        } else {
            out[o0] += r0;
            if (v1) out[o1] += r1;
        }
    }
}

// ---------------- launcher ----------------
extern "C" void kernel_launch(void* const* d_in, const int* in_sizes, int n_in,
                              void* d_out, int out_size) {
    const float* x       = (const float*)d_in[0];
    const float* routing = (const float*)d_in[1];
    const int*   idxs    = (const int*)d_in[2];   // int32 (JAX x64 disabled)
    const float* w_a     = (const float*)d_in[3];
    const float* w_b     = (const float*)d_in[4];
    float*       out     = (float*)d_out;

    build_lists_kernel<<<1, 256>>>(idxs);
    phaseA_kernel<<<dim3(MAX_TILES, 2, DSPLIT), 128>>>(x, w_a);
    combine_kernel<<<(NASSIGN * 4 + 255) / 256, 256>>>(routing);
    phaseB_kernel<0><<<dim3(MAX_TILES, DOUT / 256), 256>>>(w_b, out);
    phaseB_kernel<1><<<dim3(MAX_TILES, DOUT / 256), 256>>>(w_b, out);
}

// round 3
// speedup vs baseline: 1.1379x; 1.1379x over previous
#include <cuda_runtime.h>
#include <cuda_bf16.h>

// Problem constants
#define NTOK   4096      // B*S
#define DIN    2048
#define DOUT   2048
#define NEXP   16
#define RANK   16
#define TOPK   2
#define NASSIGN (NTOK*TOPK)   // 8192
#define ALPHA  2.0f
#define DSPLIT 8              // phase-A reduction split
#define TILE_T 128            // tokens per tile
#define TSPLIT 4              // phase-B token split (32 tokens per block)
#define MAX_TILES 64

typedef unsigned long long ull;

// ---------------- packed f32x2 helpers (FFMA2 via PTX) ----------------
__device__ __forceinline__ void fma2(ull &acc, ull a, ull b) {
    asm("fma.rn.f32x2 %0, %1, %2, %0;" : "+l"(acc) : "l"(a), "l"(b));
}
__device__ __forceinline__ ull add2(ull a, ull b) {
    ull r; asm("add.rn.f32x2 %0, %1, %2;" : "=l"(r) : "l"(a), "l"(b)); return r;
}
__device__ __forceinline__ float hadd2(ull v) {
    float lo, hi; asm("mov.b64 {%0,%1}, %2;" : "=f"(lo), "=f"(hi) : "l"(v));
    return lo + hi;
}

// ---------------- device scratch ----------------
__device__ int   d_ntiles[2];
__device__ int4  d_tiles[2][MAX_TILES];      // {expert, start, cnt, pad}
__device__ int   d_list[2][NTOK];            // token ids grouped by (k, expert)
__device__ float d_part[DSPLIT][NASSIGN * RANK];  // phase-A partial dots

// ---------------- kernel 1: build per-(k,expert) token lists ----------------
__global__ void build_lists_kernel(const int* __restrict__ idxs) {
    __shared__ int s_cnt[32], s_base[32], s_run[32];
    int tid = threadIdx.x;
    if (tid < 32) s_cnt[tid] = 0;
    __syncthreads();
    for (int i = tid; i < NASSIGN; i += blockDim.x) {
        int e = idxs[i] & 15;
        int k = i & 1;
        atomicAdd(&s_cnt[k * 16 + e], 1);
    }
    __syncthreads();
    if (tid == 0) {
        int o0 = 0, o1 = 0;
        for (int e = 0; e < 16; e++) {
            s_base[e]      = o0; o0 += s_cnt[e];
            s_base[16 + e] = o1; o1 += s_cnt[16 + e];
        }
    }
    __syncthreads();
    if (tid < 32) s_run[tid] = s_base[tid];
    __syncthreads();
    for (int i = tid; i < NASSIGN; i += blockDim.x) {
        int e = idxs[i] & 15;
        int k = i & 1;
        int pos = atomicAdd(&s_run[k * 16 + e], 1);
        d_list[k][pos] = i >> 1;
    }
    __syncthreads();
    if (tid < 2) {
        int k = tid, nt = 0;
        for (int e = 0; e < 16; e++) {
            int c  = s_cnt[k * 16 + e];
            int st = s_base[k * 16 + e];
            for (int o = 0; o < c; o += TILE_T) {
                int cc = c - o; if (cc > TILE_T) cc = TILE_T;
                d_tiles[k][nt] = make_int4(e, st + o, cc, 0);
                nt++;
            }
        }
        d_ntiles[k] = nt;
    }
}

// ---------------- kernel 2: phase A ----------------
// grid (MAX_TILES, 2, DSPLIT), block 256: 2 threads per token (rank halves).
__global__ __launch_bounds__(256) void phaseA_kernel(const float* __restrict__ x,
                                                     const float* __restrict__ w_a) {
    int k  = blockIdx.y;
    int ti = blockIdx.x;
    if (ti >= d_ntiles[k]) return;
    int4 tl = d_tiles[k][ti];
    int e = tl.x, start = tl.y, cnt = tl.z;
    int ds = blockIdx.z;

    __shared__ float sx[128 * 68];   // 128 tokens x 64 floats, pad 68
    __shared__ float sw[16 * 68];
    __shared__ int   s_tok[128];

    int tid = threadIdx.x;
    int j2  = tid >> 1;        // token slot 0..127
    int rh  = tid & 1;         // rank half

    if (tid < 128) {
        int jcl = tid < cnt ? tid : (cnt - 1);
        s_tok[tid] = d_list[k][start + jcl];
    }
    __syncthreads();

    const float* wa_e = w_a + (size_t)e * RANK * DIN;
    int dbase0 = ds * (DIN / DSPLIT);   // 256-wide slice

    ull acc[8];
#pragma unroll
    for (int r = 0; r < 8; r++) acc[r] = 0ull;

    for (int ch = 0; ch < (DIN / DSPLIT) / 64; ch++) {   // 4 chunks of 64
        int db = dbase0 + ch * 64;
        // stage x: 128 tok x 16 float4 = 2048 f4 over 256 threads
#pragma unroll
        for (int it = 0; it < 8; it++) {
            int l = it * 256 + tid;
            int tok = l >> 4, c4 = l & 15;
            float4 v = *(const float4*)(x + (size_t)s_tok[tok] * DIN + db + c4 * 4);
            *(float4*)(sx + tok * 68 + c4 * 4) = v;
        }
        // stage w: 16 rows x 16 float4 = 256 f4
        {
            int r = tid >> 4, c4 = tid & 15;
            *(float4*)(sw + r * 68 + c4 * 4) =
                *(const float4*)(wa_e + (size_t)r * DIN + db + c4 * 4);
        }
        __syncthreads();

        const float* sxr = sx + j2 * 68;
        const float* swr = sw + (rh * 8) * 68;
#pragma unroll
        for (int c4 = 0; c4 < 16; c4++) {
            ulonglong2 xv = *(const ulonglong2*)(sxr + c4 * 4);
#pragma unroll
            for (int r = 0; r < 8; r++) {
                ulonglong2 wv = *(const ulonglong2*)(swr + r * 68 + c4 * 4); // broadcast
                fma2(acc[r], xv.x, wv.x);
                fma2(acc[r], xv.y, wv.y);
            }
        }
        __syncthreads();
    }

    if (j2 < cnt) {
        int a = s_tok[j2] * 2 + k;
        float* p = &d_part[ds][(size_t)a * RANK + rh * 8];
        float4 v;
#pragma unroll
        for (int q = 0; q < 2; q++) {
            v.x = hadd2(acc[q * 4 + 0]);
            v.y = hadd2(acc[q * 4 + 1]);
            v.z = hadd2(acc[q * 4 + 2]);
            v.w = hadd2(acc[q * 4 + 3]);
            *(float4*)(p + q * 4) = v;
        }
    }
}

// ---------------- kernels 3/4: phase B (combine+silu fused into staging) ----------------
// grid (MAX_TILES, DOUT/256, TSPLIT), block 256. lane = d; 32 tokens per block.
template <int KK>
__global__ __launch_bounds__(256) void phaseB_kernel(const float* __restrict__ w_b,
                                                     const float* __restrict__ routing,
                                                     float* __restrict__ out) {
    int ti = blockIdx.x;
    if (ti >= d_ntiles[KK]) return;
    int4 tl = d_tiles[KK][ti];
    int e = tl.x, start = tl.y, cnt = tl.z;

    int z   = blockIdx.z;
    int t0i = z * (TILE_T / TSPLIT);          // window start within tile
    int cl  = cnt - t0i;                       // window count
    if (cl <= 0) return;
    if (cl > TILE_T / TSPLIT) cl = TILE_T / TSPLIT;

    __shared__ float sg[(TILE_T / TSPLIT) * 16];   // 32 tokens x 16 ranks
    __shared__ int   s_tok[TILE_T / TSPLIT];

    int tid = threadIdx.x;

    if (tid < TILE_T / TSPLIT) {
        int jcl = tid < cl ? tid : (cl - 1);
        s_tok[tid] = d_list[KK][start + t0i + jcl];
    }
    // combine partials + silu + routing*alpha -> sg
    if (tid < (TILE_T / TSPLIT) * 4) {
        int tl_ = tid >> 2, q = tid & 3;
        int jcl = tl_ < cl ? tl_ : (cl - 1);
        int t   = d_list[KK][start + t0i + jcl];
        int a   = t * 2 + KK;
        size_t off = (size_t)a * RANK + q * 4;
        float4 s = *(const float4*)(&d_part[0][off]);
#pragma unroll
        for (int ds = 1; ds < DSPLIT; ds++) {
            float4 p = *(const float4*)(&d_part[ds][off]);
            s.x += p.x; s.y += p.y; s.z += p.z; s.w += p.w;
        }
        float rs = routing[a] * ALPHA;
        float4 g;
        g.x = rs * s.x * (1.0f / (1.0f + __expf(-s.x)));
        g.y = rs * s.y * (1.0f / (1.0f + __expf(-s.y)));
        g.z = rs * s.z * (1.0f / (1.0f + __expf(-s.z)));
        g.w = rs * s.w * (1.0f / (1.0f + __expf(-s.w)));
        *(float4*)(sg + tl_ * 16 + q * 4) = g;
    }
    __syncthreads();

    int d = blockIdx.y * 256 + tid;
    const ulonglong2* wb = (const ulonglong2*)(w_b + ((size_t)e * DOUT + d) * RANK);
    ulonglong2 w0 = wb[0], w1 = wb[1], w2 = wb[2], w3 = wb[3];

    for (int j = 0; j < cl; j += 4) {
        float r[4];
#pragma unroll
        for (int u = 0; u < 4; u++) {
            int jj = j + u; if (jj >= cl) jj = cl - 1;
            const ulonglong2* g = (const ulonglong2*)(sg + jj * 16);
            ulonglong2 ga = g[0], gb = g[1], gc = g[2], gd = g[3];
            ull a0 = 0ull, a1 = 0ull;
            fma2(a0, ga.x, w0.x); fma2(a1, ga.y, w0.y);
            fma2(a0, gb.x, w1.x); fma2(a1, gb.y, w1.y);
            fma2(a0, gc.x, w2.x); fma2(a1, gc.y, w2.y);
            fma2(a0, gd.x, w3.x); fma2(a1, gd.y, w3.y);
            r[u] = hadd2(add2(a0, a1));
        }
#pragma unroll
        for (int u = 0; u < 4; u++) {
            if (j + u < cl) {
                size_t o = (size_t)s_tok[j + u] * DOUT + d;
                if (KK == 0) out[o] = r[u];
                else         out[o] += r[u];
            }
        }
    }
}

// ---------------- launcher ----------------
extern "C" void kernel_launch(void* const* d_in, const int* in_sizes, int n_in,
                              void* d_out, int out_size) {
    const float* x       = (const float*)d_in[0];
    const float* routing = (const float*)d_in[1];
    const int*   idxs    = (const int*)d_in[2];   // int32 (JAX x64 disabled)
    const float* w_a     = (const float*)d_in[3];
    const float* w_b     = (const float*)d_in[4];
    float*       out     = (float*)d_out;

    build_lists_kernel<<<1, 256>>>(idxs);
    phaseA_kernel<<<dim3(MAX_TILES, 2, DSPLIT), 256>>>(x, w_a);
    phaseB_kernel<0><<<dim3(MAX_TILES, DOUT / 256, TSPLIT), 256>>>(w_b, routing, out);
    phaseB_kernel<1><<<dim3(MAX_TILES, DOUT / 256, TSPLIT), 256>>>(w_b, routing, out);
}

// round 4
// speedup vs baseline: 1.1529x; 1.0132x over previous
#include <cuda_runtime.h>
#include <cuda_bf16.h>

// Problem constants
#define NTOK   4096      // B*S
#define DIN    2048
#define DOUT   2048
#define NEXP   16
#define RANK   16
#define TOPK   2
#define NASSIGN (NTOK*TOPK)   // 8192
#define ALPHA  2.0f
#define DSPLIT 16             // phase-A reduction split
#define TILE_T 128            // tokens per tile
#define TSPLIT 4              // phase-B token split (32 tokens per block)
#define GRP    8              // phase-B pipeline group
#define MAX_TILES 64

typedef unsigned long long ull;

// ---------------- packed f32x2 helpers (FFMA2 via PTX) ----------------
__device__ __forceinline__ void fma2(ull &acc, ull a, ull b) {
    asm("fma.rn.f32x2 %0, %1, %2, %0;" : "+l"(acc) : "l"(a), "l"(b));
}
__device__ __forceinline__ ull add2(ull a, ull b) {
    ull r; asm("add.rn.f32x2 %0, %1, %2;" : "=l"(r) : "l"(a), "l"(b)); return r;
}
__device__ __forceinline__ float hadd2(ull v) {
    float lo, hi; asm("mov.b64 {%0,%1}, %2;" : "=f"(lo), "=f"(hi) : "l"(v));
    return lo + hi;
}

// ---------------- device scratch ----------------
__device__ int   d_ntiles[2];
__device__ int4  d_tiles[2][MAX_TILES];      // {expert, start, cnt, pad}
__device__ int   d_list[2][NTOK];            // token ids grouped by (k, expert)
__device__ float d_part[DSPLIT][NASSIGN * RANK];  // phase-A partial dots

// ---------------- kernel 1: build per-(k,expert) token lists ----------------
__global__ void build_lists_kernel(const int* __restrict__ idxs) {
    __shared__ int s_cnt[32], s_base[32], s_run[32];
    int tid = threadIdx.x;
    if (tid < 32) s_cnt[tid] = 0;
    __syncthreads();
    for (int i = tid; i < NASSIGN; i += blockDim.x) {
        int e = idxs[i] & 15;
        int k = i & 1;
        atomicAdd(&s_cnt[k * 16 + e], 1);
    }
    __syncthreads();
    if (tid == 0) {
        int o0 = 0, o1 = 0;
        for (int e = 0; e < 16; e++) {
            s_base[e]      = o0; o0 += s_cnt[e];
            s_base[16 + e] = o1; o1 += s_cnt[16 + e];
        }
    }
    __syncthreads();
    if (tid < 32) s_run[tid] = s_base[tid];
    __syncthreads();
    for (int i = tid; i < NASSIGN; i += blockDim.x) {
        int e = idxs[i] & 15;
        int k = i & 1;
        int pos = atomicAdd(&s_run[k * 16 + e], 1);
        d_list[k][pos] = i >> 1;
    }
    __syncthreads();
    if (tid < 2) {
        int k = tid, nt = 0;
        for (int e = 0; e < 16; e++) {
            int c  = s_cnt[k * 16 + e];
            int st = s_base[k * 16 + e];
            for (int o = 0; o < c; o += TILE_T) {
                int cc = c - o; if (cc > TILE_T) cc = TILE_T;
                d_tiles[k][nt] = make_int4(e, st + o, cc, 0);
                nt++;
            }
        }
        d_ntiles[k] = nt;
    }
}

// ---------------- kernel 2: phase A ----------------
// grid (MAX_TILES, 2, DSPLIT), block 256: 2 threads per token (rank halves).
__global__ __launch_bounds__(256) void phaseA_kernel(const float* __restrict__ x,
                                                     const float* __restrict__ w_a) {
    int k  = blockIdx.y;
    int ti = blockIdx.x;
    if (ti >= d_ntiles[k]) return;
    int4 tl = d_tiles[k][ti];
    int e = tl.x, start = tl.y, cnt = tl.z;
    int ds = blockIdx.z;

    __shared__ float sx[128 * 68];   // 128 tokens x 64 floats, pad 68
    __shared__ float sw[16 * 68];
    __shared__ int   s_tok[128];

    int tid = threadIdx.x;
    int j2  = tid >> 1;        // token slot 0..127
    int rh  = tid & 1;         // rank half

    if (tid < 128) {
        int jcl = tid < cnt ? tid : (cnt - 1);
        s_tok[tid] = d_list[k][start + jcl];
    }
    __syncthreads();

    const float* wa_e = w_a + (size_t)e * RANK * DIN;
    int dbase0 = ds * (DIN / DSPLIT);   // 128-wide slice

    ull acc[8];
#pragma unroll
    for (int r = 0; r < 8; r++) acc[r] = 0ull;

#pragma unroll
    for (int ch = 0; ch < (DIN / DSPLIT) / 64; ch++) {   // 2 chunks of 64
        int db = dbase0 + ch * 64;
        // stage x: 128 tok x 16 float4 = 2048 f4 over 256 threads
#pragma unroll
        for (int it = 0; it < 8; it++) {
            int l = it * 256 + tid;
            int tok = l >> 4, c4 = l & 15;
            float4 v = *(const float4*)(x + (size_t)s_tok[tok] * DIN + db + c4 * 4);
            *(float4*)(sx + tok * 68 + c4 * 4) = v;
        }
        // stage w: 16 rows x 16 float4 = 256 f4
        {
            int r = tid >> 4, c4 = tid & 15;
            *(float4*)(sw + r * 68 + c4 * 4) =
                *(const float4*)(wa_e + (size_t)r * DIN + db + c4 * 4);
        }
        __syncthreads();

        const float* sxr = sx + j2 * 68;
        const float* swr = sw + (rh * 8) * 68;
#pragma unroll
        for (int c4 = 0; c4 < 16; c4++) {
            ulonglong2 xv = *(const ulonglong2*)(sxr + c4 * 4);
#pragma unroll
            for (int r = 0; r < 8; r++) {
                ulonglong2 wv = *(const ulonglong2*)(swr + r * 68 + c4 * 4); // broadcast
                fma2(acc[r], xv.x, wv.x);
                fma2(acc[r], xv.y, wv.y);
            }
        }
        __syncthreads();
    }

    if (j2 < cnt) {
        int a = s_tok[j2] * 2 + k;
        float* p = &d_part[ds][(size_t)a * RANK + rh * 8];
        float4 v;
#pragma unroll
        for (int q = 0; q < 2; q++) {
            v.x = hadd2(acc[q * 4 + 0]);
            v.y = hadd2(acc[q * 4 + 1]);
            v.z = hadd2(acc[q * 4 + 2]);
            v.w = hadd2(acc[q * 4 + 3]);
            *(float4*)(p + q * 4) = v;
        }
    }
}

// ---------------- kernels 3/4: phase B (combine+silu fused; pipelined out RMW) ----------------
// grid (MAX_TILES, DOUT/256, TSPLIT), block 256. lane = d; 32 tokens per block.
template <int KK>
__global__ __launch_bounds__(256) void phaseB_kernel(const float* __restrict__ w_b,
                                                     const float* __restrict__ routing,
                                                     float* __restrict__ out) {
    int ti = blockIdx.x;
    if (ti >= d_ntiles[KK]) return;
    int4 tl = d_tiles[KK][ti];
    int e = tl.x, start = tl.y, cnt = tl.z;

    int z   = blockIdx.z;
    int t0i = z * (TILE_T / TSPLIT);          // window start within tile
    int cl  = cnt - t0i;                       // window count
    if (cl <= 0) return;
    if (cl > TILE_T / TSPLIT) cl = TILE_T / TSPLIT;

    __shared__ float sg[(TILE_T / TSPLIT) * 16];   // 32 tokens x 16 ranks
    __shared__ int   s_tok[TILE_T / TSPLIT];

    int tid = threadIdx.x;

    if (tid < TILE_T / TSPLIT) {
        int jcl = tid < cl ? tid : (cl - 1);
        s_tok[tid] = d_list[KK][start + t0i + jcl];
    }
    // combine partials + silu + routing*alpha -> sg
    if (tid < (TILE_T / TSPLIT) * 4) {
        int tl_ = tid >> 2, q = tid & 3;
        int jcl = tl_ < cl ? tl_ : (cl - 1);
        int t   = d_list[KK][start + t0i + jcl];
        int a   = t * 2 + KK;
        size_t off = (size_t)a * RANK + q * 4;
        float4 s = *(const float4*)(&d_part[0][off]);
#pragma unroll
        for (int ds = 1; ds < DSPLIT; ds++) {
            float4 p = *(const float4*)(&d_part[ds][off]);
            s.x += p.x; s.y += p.y; s.z += p.z; s.w += p.w;
        }
        float rs = routing[a] * ALPHA;
        float4 g;
        g.x = rs * s.x * (1.0f / (1.0f + __expf(-s.x)));
        g.y = rs * s.y * (1.0f / (1.0f + __expf(-s.y)));
        g.z = rs * s.z * (1.0f / (1.0f + __expf(-s.z)));
        g.w = rs * s.w * (1.0f / (1.0f + __expf(-s.w)));
        *(float4*)(sg + tl_ * 16 + q * 4) = g;
    }
    __syncthreads();

    int d = blockIdx.y * 256 + tid;
    const ulonglong2* wb = (const ulonglong2*)(w_b + ((size_t)e * DOUT + d) * RANK);
    ulonglong2 w0 = wb[0], w1 = wb[1], w2 = wb[2], w3 = wb[3];

    // prologue: prefetch out for group 0 (KK==1 only)
    float pref[GRP];
    if (KK == 1) {
#pragma unroll
        for (int u = 0; u < GRP; u++) {
            int jj = u < cl ? u : (cl - 1);
            pref[u] = __ldg(out + (size_t)s_tok[jj] * DOUT + d);
        }
    }

    for (int j0 = 0; j0 < cl; j0 += GRP) {
        // prefetch next group while computing this one
        float nxt[GRP];
        bool have_next = (KK == 1) && (j0 + GRP < cl);
        if (have_next) {
#pragma unroll
            for (int u = 0; u < GRP; u++) {
                int jj = j0 + GRP + u; if (jj >= cl) jj = cl - 1;
                nxt[u] = __ldg(out + (size_t)s_tok[jj] * DOUT + d);
            }
        }

        float rr[GRP];
#pragma unroll
        for (int u = 0; u < GRP; u++) {
            int jj = j0 + u; if (jj >= cl) jj = cl - 1;
            const ulonglong2* g = (const ulonglong2*)(sg + jj * 16);
            ulonglong2 ga = g[0], gb = g[1], gc = g[2], gd = g[3];
            ull a0 = 0ull, a1 = 0ull;
            fma2(a0, ga.x, w0.x); fma2(a1, ga.y, w0.y);
            fma2(a0, gb.x, w1.x); fma2(a1, gb.y, w1.y);
            fma2(a0, gc.x, w2.x); fma2(a1, gc.y, w2.y);
            fma2(a0, gd.x, w3.x); fma2(a1, gd.y, w3.y);
            rr[u] = hadd2(add2(a0, a1));
        }

#pragma unroll
        for (int u = 0; u < GRP; u++) {
            int jj = j0 + u;
            if (jj < cl) {
                size_t o = (size_t)s_tok[jj] * DOUT + d;
                out[o] = (KK == 0) ? rr[u] : (rr[u] + pref[u]);
            }
        }
        if (KK == 1) {
#pragma unroll
            for (int u = 0; u < GRP; u++) pref[u] = nxt[u];
        }
    }
}

// ---------------- launcher ----------------
extern "C" void kernel_launch(void* const* d_in, const int* in_sizes, int n_in,
                              void* d_out, int out_size) {
    const float* x       = (const float*)d_in[0];
    const float* routing = (const float*)d_in[1];
    const int*   idxs    = (const int*)d_in[2];   // int32 (JAX x64 disabled)
    const float* w_a     = (const float*)d_in[3];
    const float* w_b     = (const float*)d_in[4];
    float*       out     = (float*)d_out;

    build_lists_kernel<<<1, 256>>>(idxs);
    phaseA_kernel<<<dim3(MAX_TILES, 2, DSPLIT), 256>>>(x, w_a);
    phaseB_kernel<0><<<dim3(MAX_TILES, DOUT / 256, TSPLIT), 256>>>(w_b, routing, out);
    phaseB_kernel<1><<<dim3(MAX_TILES, DOUT / 256, TSPLIT), 256>>>(w_b, routing, out);
}

// round 5
// speedup vs baseline: 1.2463x; 1.0810x over previous
#include <cuda_runtime.h>
#include <cuda_bf16.h>

// Problem constants
#define NTOK   4096      // B*S
#define DIN    2048
#define DOUT   2048
#define NEXP   16
#define RANK   16
#define TOPK   2
#define NASSIGN (NTOK*TOPK)   // 8192
#define ALPHA  2.0f
#define DSPLIT 16             // phase-A reduction split
#define TILE_T 128            // tokens per tile
#define WIN    64             // phase-B token window per block
#define GRP    8              // phase-B inner group
#define MAX_TILES 64

typedef unsigned long long ull;

// ---------------- packed f32x2 helpers (FFMA2 via PTX) ----------------
__device__ __forceinline__ void fma2(ull &acc, ull a, ull b) {
    asm("fma.rn.f32x2 %0, %1, %2, %0;" : "+l"(acc) : "l"(a), "l"(b));
}
__device__ __forceinline__ ull add2(ull a, ull b) {
    ull r; asm("add.rn.f32x2 %0, %1, %2;" : "=l"(r) : "l"(a), "l"(b)); return r;
}
__device__ __forceinline__ float hadd2(ull v) {
    float lo, hi; asm("mov.b64 {%0,%1}, %2;" : "=f"(lo), "=f"(hi) : "l"(v));
    return lo + hi;
}

// ---------------- device scratch ----------------
__device__ int   d_ntiles[2];
__device__ int4  d_tiles[2][MAX_TILES];      // {expert, start, cnt, pad}
__device__ int   d_list[2][NTOK];            // token ids grouped by (k, expert)
__device__ float d_part[DSPLIT][NASSIGN * RANK];  // phase-A partial dots
__device__ float d_gact[NASSIGN * RANK];     // routing*alpha*silu(a)

// ---------------- kernel 1: build per-(k,expert) token lists (2 blocks, no global atomics) ----------------
__global__ __launch_bounds__(256) void build_lists_kernel(const int* __restrict__ idxs) {
    int k   = blockIdx.x;
    int tid = threadIdx.x, w = tid >> 5, lane = tid & 31;
    __shared__ int hist[8][16];
    __shared__ int wofs[8][16];
    __shared__ int base[16], totals[16];

    if (tid < 128) ((int*)hist)[tid] = 0;
    __syncthreads();

    // pass 1: per-warp histograms (smem atomics hit warp-private counters only)
#pragma unroll 4
    for (int it = 0; it < 16; it++) {
        int t = w * 512 + it * 32 + lane;
        int e = idxs[2 * t + k] & 15;
        atomicAdd(&hist[w][e], 1);
    }
    __syncthreads();

    if (tid < 16) {
        int e = tid, s = 0;
#pragma unroll
        for (int ww = 0; ww < 8; ww++) s += hist[ww][e];
        totals[e] = s;
    }
    __syncthreads();
    if (tid == 0) {
        int o = 0;
        for (int e = 0; e < 16; e++) { base[e] = o; o += totals[e]; }
    }
    __syncthreads();
    if (tid < 16) {
        int e = tid, o = base[e];
#pragma unroll
        for (int ww = 0; ww < 8; ww++) { wofs[ww][e] = o; o += hist[ww][e]; }
    }
    __syncthreads();

    // pass 2: deterministic scatter via match_any rank
    for (int it = 0; it < 16; it++) {
        int t = w * 512 + it * 32 + lane;
        int e = idxs[2 * t + k] & 15;
        unsigned mask = __match_any_sync(0xffffffffu, e);
        int rank = __popc(mask & ((1u << lane) - 1u));
        int posb = wofs[w][e];
        d_list[k][posb + rank] = t;
        __syncwarp();
        if (rank == __popc(mask) - 1) wofs[w][e] = posb + rank + 1;
        __syncwarp();
    }
    __syncthreads();

    if (tid == 0) {
        int nt = 0;
        for (int e = 0; e < 16; e++) {
            int c = totals[e], st = base[e];
            for (int o = 0; o < c; o += TILE_T) {
                int cc = c - o; if (cc > TILE_T) cc = TILE_T;
                d_tiles[k][nt] = make_int4(e, st + o, cc, 0);
                nt++;
            }
        }
        d_ntiles[k] = nt;
    }
}

// ---------------- kernel 2: phase A ----------------
// grid (MAX_TILES, 2, DSPLIT), block 256: 2 threads per token (rank halves).
__global__ __launch_bounds__(256) void phaseA_kernel(const float* __restrict__ x,
                                                     const float* __restrict__ w_a) {
    int k  = blockIdx.y;
    int ti = blockIdx.x;
    if (ti >= d_ntiles[k]) return;
    int4 tl = d_tiles[k][ti];
    int e = tl.x, start = tl.y, cnt = tl.z;
    int ds = blockIdx.z;

    __shared__ float sx[128 * 68];
    __shared__ float sw[16 * 68];
    __shared__ int   s_tok[128];

    int tid = threadIdx.x;
    int j2  = tid >> 1;        // token slot
    int rh  = tid & 1;         // rank half

    if (tid < 128) {
        int jcl = tid < cnt ? tid : (cnt - 1);
        s_tok[tid] = d_list[k][start + jcl];
    }
    __syncthreads();

    const float* wa_e = w_a + (size_t)e * RANK * DIN;
    int dbase0 = ds * (DIN / DSPLIT);   // 128-wide slice

    ull acc[8];
#pragma unroll
    for (int r = 0; r < 8; r++) acc[r] = 0ull;

#pragma unroll
    for (int ch = 0; ch < (DIN / DSPLIT) / 64; ch++) {   // 2 chunks of 64
        int db = dbase0 + ch * 64;
#pragma unroll
        for (int it = 0; it < 8; it++) {
            int l = it * 256 + tid;
            int tok = l >> 4, c4 = l & 15;
            float4 v = *(const float4*)(x + (size_t)s_tok[tok] * DIN + db + c4 * 4);
            *(float4*)(sx + tok * 68 + c4 * 4) = v;
        }
        {
            int r = tid >> 4, c4 = tid & 15;
            *(float4*)(sw + r * 68 + c4 * 4) =
                *(const float4*)(wa_e + (size_t)r * DIN + db + c4 * 4);
        }
        __syncthreads();

        const float* sxr = sx + j2 * 68;
        const float* swr = sw + (rh * 8) * 68;
#pragma unroll
        for (int c4 = 0; c4 < 16; c4++) {
            ulonglong2 xv = *(const ulonglong2*)(sxr + c4 * 4);
#pragma unroll
            for (int r = 0; r < 8; r++) {
                ulonglong2 wv = *(const ulonglong2*)(swr + r * 68 + c4 * 4);
                fma2(acc[r], xv.x, wv.x);
                fma2(acc[r], xv.y, wv.y);
            }
        }
        __syncthreads();
    }

    if (j2 < cnt) {
        int a = s_tok[j2] * 2 + k;
        float* p = &d_part[ds][(size_t)a * RANK + rh * 8];
        float4 v;
#pragma unroll
        for (int q = 0; q < 2; q++) {
            v.x = hadd2(acc[q * 4 + 0]);
            v.y = hadd2(acc[q * 4 + 1]);
            v.z = hadd2(acc[q * 4 + 2]);
            v.w = hadd2(acc[q * 4 + 3]);
            *(float4*)(p + q * 4) = v;
        }
    }
}

// ---------------- kernel 3: combine partials + silu + routing*alpha ----------------
__global__ void combine_kernel(const float* __restrict__ routing) {
    int idx = blockIdx.x * blockDim.x + threadIdx.x;   // NASSIGN*4 float4 groups
    if (idx >= NASSIGN * 4) return;
    int a = idx >> 2, q = idx & 3;
    size_t off = (size_t)a * RANK + q * 4;
    float4 s = *(const float4*)(&d_part[0][off]);
#pragma unroll
    for (int ds = 1; ds < DSPLIT; ds++) {
        float4 p = *(const float4*)(&d_part[ds][off]);
        s.x += p.x; s.y += p.y; s.z += p.z; s.w += p.w;
    }
    float rs = routing[a] * ALPHA;
    float4 g;
    g.x = rs * s.x * (1.0f / (1.0f + __expf(-s.x)));
    g.y = rs * s.y * (1.0f / (1.0f + __expf(-s.y)));
    g.z = rs * s.z * (1.0f / (1.0f + __expf(-s.z)));
    g.w = rs * s.w * (1.0f / (1.0f + __expf(-s.w)));
    *(float4*)(d_gact + off) = g;
}

// ---------------- kernel 4: phase B — single pass, both k, RED accumulation ----------------
// grid (MAX_TILES, DOUT/256, 2*TILE_T/WIN), block 256. z = (zslice<<1)|k.
__global__ __launch_bounds__(256) void phaseB_kernel(const float* __restrict__ w_b,
                                                     float* __restrict__ out) {
    int kk = blockIdx.z & 1;
    int zs = blockIdx.z >> 1;
    int ti = blockIdx.x;
    if (ti >= d_ntiles[kk]) return;
    int4 tl = d_tiles[kk][ti];
    int e = tl.x, start = tl.y, cnt = tl.z;

    int t0i = zs * WIN;
    int cl  = cnt - t0i;
    if (cl <= 0) return;
    if (cl > WIN) cl = WIN;

    __shared__ float sg[WIN * 16];
    __shared__ int   s_tok[WIN];

    int tid = threadIdx.x;
    if (tid < WIN) {
        int jcl = tid < cl ? tid : (cl - 1);
        s_tok[tid] = d_list[kk][start + t0i + jcl];
    }
    {   // stage g: 64 tokens x 4 float4 over 256 threads
        int j = tid >> 2, q = tid & 3;
        int jcl = j < cl ? j : (cl - 1);
        int t = d_list[kk][start + t0i + jcl];
        int a = t * 2 + kk;
        *(float4*)(sg + j * 16 + q * 4) = *(const float4*)(d_gact + (size_t)a * RANK + q * 4);
    }
    __syncthreads();

    int d = blockIdx.y * 256 + tid;
    const ulonglong2* wb = (const ulonglong2*)(w_b + ((size_t)e * DOUT + d) * RANK);
    ulonglong2 w0 = wb[0], w1 = wb[1], w2 = wb[2], w3 = wb[3];

    for (int j0 = 0; j0 < cl; j0 += GRP) {
        float rr[GRP];
#pragma unroll
        for (int u = 0; u < GRP; u++) {
            int jj = j0 + u; if (jj >= cl) jj = cl - 1;
            const ulonglong2* g = (const ulonglong2*)(sg + jj * 16);
            ulonglong2 ga = g[0], gb = g[1], gc = g[2], gd = g[3];
            ull a0 = 0ull, a1 = 0ull;
            fma2(a0, ga.x, w0.x); fma2(a1, ga.y, w0.y);
            fma2(a0, gb.x, w1.x); fma2(a1, gb.y, w1.y);
            fma2(a0, gc.x, w2.x); fma2(a1, gc.y, w2.y);
            fma2(a0, gd.x, w3.x); fma2(a1, gd.y, w3.y);
            rr[u] = hadd2(add2(a0, a1));
        }
#pragma unroll
        for (int u = 0; u < GRP; u++) {
            int jj = j0 + u;
            if (jj < cl) {
                atomicAdd(out + (size_t)s_tok[jj] * DOUT + d, rr[u]);  // REDG (result unused)
            }
        }
    }
}

// ---------------- launcher ----------------
extern "C" void kernel_launch(void* const* d_in, const int* in_sizes, int n_in,
                              void* d_out, int out_size) {
    const float* x       = (const float*)d_in[0];
    const float* routing = (const float*)d_in[1];
    const int*   idxs    = (const int*)d_in[2];   // int32 (JAX x64 disabled)
    const float* w_a     = (const float*)d_in[3];
    const float* w_b     = (const float*)d_in[4];
    float*       out     = (float*)d_out;

    cudaMemsetAsync(out, 0, (size_t)out_size * sizeof(float));
    build_lists_kernel<<<2, 256>>>(idxs);
    phaseA_kernel<<<dim3(MAX_TILES, 2, DSPLIT), 256>>>(x, w_a);
    combine_kernel<<<(NASSIGN * 4 + 255) / 256, 256>>>(routing);
    phaseB_kernel<<<dim3(MAX_TILES, DOUT / 256, 2 * TILE_T / WIN), 256>>>(w_b, out);
}

// round 6
// speedup vs baseline: 1.7467x; 1.4015x over previous
#include <cuda_runtime.h>
#include <cuda_bf16.h>

// Problem constants
#define NTOK   4096      // B*S
#define DIN    2048
#define DOUT   2048
#define NEXP   16
#define RANK   16
#define TOPK   2
#define NASSIGN (NTOK*TOPK)   // 8192
#define ALPHA  2.0f
#define DSPLIT 8              // phase-A reduction split (4 chunks of 64 per block)
#define TILE_T 128            // tokens per tile
#define WIN    64             // phase-B token window per block
#define GRP    4              // phase-B inner group
#define MAX_TILES 64

#define A_BUF_FLOATS (128 * 68 + 16 * 68)           // sx + sw per stage buffer
#define A_SMEM_BYTES (2 * A_BUF_FLOATS * 4)          // 78336 B dynamic

typedef unsigned long long ull;

// ---------------- packed f32x2 helpers (FFMA2 via PTX) ----------------
__device__ __forceinline__ void fma2(ull &acc, ull a, ull b) {
    asm("fma.rn.f32x2 %0, %1, %2, %0;" : "+l"(acc) : "l"(a), "l"(b));
}
__device__ __forceinline__ ull add2(ull a, ull b) {
    ull r; asm("add.rn.f32x2 %0, %1, %2;" : "=l"(r) : "l"(a), "l"(b)); return r;
}
__device__ __forceinline__ float hadd2(ull v) {
    float lo, hi; asm("mov.b64 {%0,%1}, %2;" : "=f"(lo), "=f"(hi) : "l"(v));
    return lo + hi;
}
__device__ __forceinline__ void cp16(void* smem, const void* gmem) {
    unsigned sa = (unsigned)__cvta_generic_to_shared(smem);
    asm volatile("cp.async.cg.shared.global [%0], [%1], 16;" :: "r"(sa), "l"(gmem));
}
#define CP_COMMIT()  asm volatile("cp.async.commit_group;")
#define CP_WAIT(n)   asm volatile("cp.async.wait_group %0;" :: "n"(n))

// ---------------- device scratch ----------------
__device__ int   d_ntiles[2];
__device__ int4  d_tiles[2][MAX_TILES];      // {expert, start, cnt, pad}
__device__ int   d_list[2][NTOK];            // token ids grouped by (k, expert)
__device__ float d_part[DSPLIT][NASSIGN * RANK];  // phase-A partial dots
__device__ float d_gact[NASSIGN * RANK];     // routing*alpha*silu(a)

// ---------------- kernel 1: build per-(k,expert) token lists (register-prefetched) ----------------
__global__ __launch_bounds__(256) void build_lists_kernel(const int* __restrict__ idxs) {
    int k   = blockIdx.x;
    int tid = threadIdx.x, w = tid >> 5, lane = tid & 31;
    __shared__ int hist[8][16];
    __shared__ int wofs[8][16];
    __shared__ int base[16], totals[16];

    if (tid < 128) ((int*)hist)[tid] = 0;

    // prefetch all 16 expert ids into registers (independent LDGs, fully overlapped)
    int myE[16];
#pragma unroll
    for (int it = 0; it < 16; it++) {
        int t = w * 512 + it * 32 + lane;
        myE[it] = idxs[2 * t + k] & 15;
    }
    __syncthreads();
#pragma unroll
    for (int it = 0; it < 16; it++) atomicAdd(&hist[w][myE[it]], 1);
    __syncthreads();

    if (tid < 16) {
        int e = tid, s = 0;
#pragma unroll
        for (int ww = 0; ww < 8; ww++) s += hist[ww][e];
        totals[e] = s;
    }
    __syncthreads();
    if (tid == 0) {
        int o = 0;
        for (int e = 0; e < 16; e++) { base[e] = o; o += totals[e]; }
    }
    __syncthreads();
    if (tid < 16) {
        int e = tid, o = base[e];
#pragma unroll
        for (int ww = 0; ww < 8; ww++) { wofs[ww][e] = o; o += hist[ww][e]; }
    }
    __syncthreads();

    // deterministic scatter (register-resident expert ids; only smem + STG in loop)
#pragma unroll
    for (int it = 0; it < 16; it++) {
        int t = w * 512 + it * 32 + lane;
        int e = myE[it];
        unsigned mask = __match_any_sync(0xffffffffu, e);
        int rank = __popc(mask & ((1u << lane) - 1u));
        int posb = wofs[w][e];
        d_list[k][posb + rank] = t;
        __syncwarp();
        if (rank == __popc(mask) - 1) wofs[w][e] = posb + rank + 1;
        __syncwarp();
    }
    __syncthreads();

    if (tid == 0) {
        int nt = 0;
        for (int e = 0; e < 16; e++) {
            int c = totals[e], st = base[e];
            for (int o = 0; o < c; o += TILE_T) {
                int cc = c - o; if (cc > TILE_T) cc = TILE_T;
                d_tiles[k][nt] = make_int4(e, st + o, cc, 0);
                nt++;
            }
        }
        d_ntiles[k] = nt;
    }
}

// ---------------- kernel 2: phase A — cp.async double-buffered ----------------
// grid (MAX_TILES, 2, DSPLIT), block 256: 2 threads/token, rh = odd/even ranks.
__global__ __launch_bounds__(256) void phaseA_kernel(const float* __restrict__ x,
                                                     const float* __restrict__ w_a) {
    int k  = blockIdx.y;
    int ti = blockIdx.x;
    if (ti >= d_ntiles[k]) return;
    int4 tl = d_tiles[k][ti];
    int e = tl.x, start = tl.y, cnt = tl.z;
    int ds = blockIdx.z;

    extern __shared__ float dyn[];           // 2 x (sx[128*68] + sw[16*68])
    __shared__ int s_tok[128];

    int tid = threadIdx.x;
    int j2  = tid >> 1;        // token slot
    int rh  = tid & 1;         // rank parity: handles ranks {2i+rh}

    if (tid < 128) {
        int jcl = tid < cnt ? tid : (cnt - 1);
        s_tok[tid] = d_list[k][start + jcl];
    }
    __syncthreads();

    const float* wa_e = w_a + (size_t)e * RANK * DIN;
    int dbase0 = ds * (DIN / DSPLIT);        // 256-wide slice, 4 chunks of 64

    // stage chunk into buffer
    auto stage = [&](int buf, int ch) {
        float* sxb = dyn + buf * A_BUF_FLOATS;
        float* swb = sxb + 128 * 68;
        int db = dbase0 + ch * 64;
#pragma unroll
        for (int it = 0; it < 8; it++) {
            int l = it * 256 + tid;
            int tok = l >> 4, c4 = l & 15;
            cp16(sxb + tok * 68 + c4 * 4,
                 x + (size_t)s_tok[tok] * DIN + db + c4 * 4);
        }
        {
            int r = tid >> 4, c4 = tid & 15;
            cp16(swb + r * 68 + c4 * 4,
                 wa_e + (size_t)r * DIN + db + c4 * 4);
        }
        CP_COMMIT();
    };

    ull acc[8];
#pragma unroll
    for (int i = 0; i < 8; i++) acc[i] = 0ull;

    stage(0, 0);
    int buf = 0;
#pragma unroll
    for (int ch = 0; ch < 4; ch++) {
        if (ch < 3) { stage(buf ^ 1, ch + 1); CP_WAIT(1); }
        else        { CP_WAIT(0); }
        __syncthreads();

        const float* sxb = dyn + buf * A_BUF_FLOATS;
        const float* swb = sxb + 128 * 68;
        const float* sxr = sxb + j2 * 68;
        const float* swr = swb + rh * 68;    // rank 2i+rh at row offset (2i+rh)*68
#pragma unroll
        for (int c4 = 0; c4 < 16; c4++) {
            ulonglong2 xv = *(const ulonglong2*)(sxr + c4 * 4);
#pragma unroll
            for (int i = 0; i < 8; i++) {
                ulonglong2 wv = *(const ulonglong2*)(swr + (2 * i) * 68 + c4 * 4);
                fma2(acc[i], xv.x, wv.x);
                fma2(acc[i], xv.y, wv.y);
            }
        }
        __syncthreads();
        buf ^= 1;
    }

    if (j2 < cnt) {
        int a = s_tok[j2] * 2 + k;
        float* p = &d_part[ds][(size_t)a * RANK];
#pragma unroll
        for (int i = 0; i < 8; i++) p[2 * i + rh] = hadd2(acc[i]);
    }
}

// ---------------- kernel 3: combine partials + silu + routing*alpha ----------------
__global__ void combine_kernel(const float* __restrict__ routing) {
    int idx = blockIdx.x * blockDim.x + threadIdx.x;   // NASSIGN*4 float4 groups
    if (idx >= NASSIGN * 4) return;
    int a = idx >> 2, q = idx & 3;
    size_t off = (size_t)a * RANK + q * 4;
    float4 s = *(const float4*)(&d_part[0][off]);
#pragma unroll
    for (int ds = 1; ds < DSPLIT; ds++) {
        float4 p = *(const float4*)(&d_part[ds][off]);
        s.x += p.x; s.y += p.y; s.z += p.z; s.w += p.w;
    }
    float rs = routing[a] * ALPHA;
    float4 g;
    g.x = rs * s.x * (1.0f / (1.0f + __expf(-s.x)));
    g.y = rs * s.y * (1.0f / (1.0f + __expf(-s.y)));
    g.z = rs * s.z * (1.0f / (1.0f + __expf(-s.z)));
    g.w = rs * s.w * (1.0f / (1.0f + __expf(-s.w)));
    *(float4*)(d_gact + off) = g;
}

// ---------------- kernel 4: phase B — both k, 2 d's per thread, RED accumulation ----------------
// grid (MAX_TILES, DOUT/512, 4), block 256. z = (zslice<<1)|k.
__global__ __launch_bounds__(256) void phaseB_kernel(const float* __restrict__ w_b,
                                                     float* __restrict__ out) {
    int kk = blockIdx.z & 1;
    int zs = blockIdx.z >> 1;
    int ti = blockIdx.x;
    if (ti >= d_ntiles[kk]) return;
    int4 tl = d_tiles[kk][ti];
    int e = tl.x, start = tl.y, cnt = tl.z;

    int t0i = zs * WIN;
    int cl  = cnt - t0i;
    if (cl <= 0) return;
    if (cl > WIN) cl = WIN;

    __shared__ float sg[WIN * 16];
    __shared__ int   s_tok[WIN];

    int tid = threadIdx.x;
    if (tid < WIN) {
        int jcl = tid < cl ? tid : (cl - 1);
        s_tok[tid] = d_list[kk][start + t0i + jcl];
    }
    {   // stage g: 64 tokens x 4 float4 over 256 threads
        int j = tid >> 2, q = tid & 3;
        int jcl = j < cl ? j : (cl - 1);
        int t = d_list[kk][start + t0i + jcl];
        int a = t * 2 + kk;
        *(float4*)(sg + j * 16 + q * 4) = *(const float4*)(d_gact + (size_t)a * RANK + q * 4);
    }
    __syncthreads();

    int d0 = blockIdx.y * 512 + tid;
    int d1 = d0 + 256;
    const ulonglong2* wbp0 = (const ulonglong2*)(w_b + ((size_t)e * DOUT + d0) * RANK);
    const ulonglong2* wbp1 = (const ulonglong2*)(w_b + ((size_t)e * DOUT + d1) * RANK);
    ulonglong2 p0 = wbp0[0], p1 = wbp0[1], p2 = wbp0[2], p3 = wbp0[3];
    ulonglong2 q0 = wbp1[0], q1 = wbp1[1], q2 = wbp1[2], q3 = wbp1[3];

    for (int j0 = 0; j0 < cl; j0 += GRP) {
        float r0[GRP], r1[GRP];
#pragma unroll
        for (int u = 0; u < GRP; u++) {
            int jj = j0 + u; if (jj >= cl) jj = cl - 1;
            const ulonglong2* g = (const ulonglong2*)(sg + jj * 16);
            ulonglong2 ga = g[0], gb = g[1], gc = g[2], gd = g[3];
            ull a0 = 0ull, a1 = 0ull, b0 = 0ull, b1 = 0ull;
            fma2(a0, ga.x, p0.x); fma2(a1, ga.y, p0.y);
            fma2(b0, ga.x, q0.x); fma2(b1, ga.y, q0.y);
            fma2(a0, gb.x, p1.x); fma2(a1, gb.y, p1.y);
            fma2(b0, gb.x, q1.x); fma2(b1, gb.y, q1.y);
            fma2(a0, gc.x, p2.x); fma2(a1, gc.y, p2.y);
            fma2(b0, gc.x, q2.x); fma2(b1, gc.y, q2.y);
            fma2(a0, gd.x, p3.x); fma2(a1, gd.y, p3.y);
            fma2(b0, gd.x, q3.x); fma2(b1, gd.y, q3.y);
            r0[u] = hadd2(add2(a0, a1));
            r1[u] = hadd2(add2(b0, b1));
        }
#pragma unroll
        for (int u = 0; u < GRP; u++) {
            int jj = j0 + u;
            if (jj < cl) {
                size_t ob = (size_t)s_tok[jj] * DOUT;
                atomicAdd(out + ob + d0, r0[u]);   // REDG (no return)
                atomicAdd(out + ob + d1, r1[u]);
            }
        }
    }
}

// ---------------- launcher ----------------
extern "C" void kernel_launch(void* const* d_in, const int* in_sizes, int n_in,
                              void* d_out, int out_size) {
    const float* x       = (const float*)d_in[0];
    const float* routing = (const float*)d_in[1];
    const int*   idxs    = (const int*)d_in[2];   // int32 (JAX x64 disabled)
    const float* w_a     = (const float*)d_in[3];
    const float* w_b     = (const float*)d_in[4];
    float*       out     = (float*)d_out;

    cudaFuncSetAttribute(phaseA_kernel, cudaFuncAttributeMaxDynamicSharedMemorySize,
                         A_SMEM_BYTES);

    cudaMemsetAsync(out, 0, (size_t)out_size * sizeof(float));
    build_lists_kernel<<<2, 256>>>(idxs);
    phaseA_kernel<<<dim3(MAX_TILES, 2, DSPLIT), 256, A_SMEM_BYTES>>>(x, w_a);
    combine_kernel<<<(NASSIGN * 4 + 255) / 256, 256>>>(routing);
    phaseB_kernel<<<dim3(MAX_TILES, DOUT / 512, 4), 256>>>(w_b, out);
}